// round 10
// baseline (speedup 1.0000x reference)
#include <cuda_runtime.h>
#include <math.h>

// Problem constants (fixed by reference: N=50000, E=800000, C=96, H=4, CH=24)
#define NMAX 50000
#define EMAX 800000
#define C 96
#define NH 4
#define CH 24
#define NEG_SLOPE 0.2f
#define LN_EPS 1e-5f

// ---------------- device scratch (static, no allocation) ----------------
__device__ float g_h[NMAX * C];        // 19.2 MB
__device__ float g_asrc[NMAX * NH];
__device__ float g_adst[NMAX * NH];
__device__ int   g_deg[NMAX];
__device__ int   g_rowptr[NMAX + 1];
__device__ int   g_widx[NMAX];
__device__ int   g_csr[EMAX];

#define SCAN_TILE 1024
#define NBLK_SCAN ((NMAX + SCAN_TILE - 1) / SCAN_TILE)   // 49
__device__ int g_bsum[NBLK_SCAN];

// ---------------- zero counters (deg + scan flags) ----------------
__global__ void kzero(int n) {
    int i = blockIdx.x * blockDim.x + threadIdx.x;
    if (i < n) g_deg[i] = 0;
    if (i < NBLK_SCAN) g_bsum[i] = 0;
}

// ================= GEMM tile (h = x@W + fused attention coeffs) =================
#define GR 64
#define GEMM_THREADS 192
#define KS 24
#define XS_PAD 68

__device__ __forceinline__ void gemm_block(int gb,
                                           const float* __restrict__ x,
                                           const float* __restrict__ W,
                                           const float* __restrict__ att_src,
                                           const float* __restrict__ att_dst,
                                           int n,
                                           float* Ws, float (*xs)[XS_PAD], float* red) {
    int t = threadIdx.x;
    int r0 = gb * GR;
    int rows = min(GR, n - r0);

    for (int idx = t; idx < 2 * GR * NH; idx += GEMM_THREADS) red[idx] = 0.f;

    int tc = t % 24;
    int tr = t / 24;
    float acc[8][4];
#pragma unroll
    for (int p = 0; p < 8; p++)
#pragma unroll
        for (int q = 0; q < 4; q++) acc[p][q] = 0.f;

    for (int ks = 0; ks < 96; ks += KS) {
        for (int idx = t; idx < KS * 96; idx += GEMM_THREADS)
            Ws[idx] = W[(ks + idx / 96) * 96 + idx % 96];
        for (int idx = t; idx < rows * KS; idx += GEMM_THREADS) {
            int r = idx / KS, k = idx % KS;
            xs[k][r] = x[(r0 + r) * 96 + ks + k];
        }
        __syncthreads();
#pragma unroll 4
        for (int k = 0; k < KS; k++) {
            float4 wv = *(const float4*)&Ws[k * 96 + tc * 4];
            float4 xa = *(const float4*)&xs[k][tr * 8];
            float4 xb = *(const float4*)&xs[k][tr * 8 + 4];
            float xv[8] = {xa.x, xa.y, xa.z, xa.w, xb.x, xb.y, xb.z, xb.w};
#pragma unroll
            for (int p = 0; p < 8; p++) {
                acc[p][0] += xv[p] * wv.x;
                acc[p][1] += xv[p] * wv.y;
                acc[p][2] += xv[p] * wv.z;
                acc[p][3] += xv[p] * wv.w;
            }
        }
        __syncthreads();
    }

#pragma unroll
    for (int p = 0; p < 8; p++) {
        int gr = r0 + tr * 8 + p;
        if (gr < n) {
            float4 st = make_float4(acc[p][0], acc[p][1], acc[p][2], acc[p][3]);
            *(float4*)&g_h[gr * 96 + tc * 4] = st;
        }
    }

    int col0 = tc * 4;
    int head = tc / 6;
    float4 asv = *(const float4*)&att_src[col0];
    float4 adv = *(const float4*)&att_dst[col0];
#pragma unroll
    for (int p = 0; p < 8; p++) {
        int lr = tr * 8 + p;
        if (lr < rows) {
            float ps = acc[p][0] * asv.x + acc[p][1] * asv.y + acc[p][2] * asv.z + acc[p][3] * asv.w;
            float pd = acc[p][0] * adv.x + acc[p][1] * adv.y + acc[p][2] * adv.z + acc[p][3] * adv.w;
            atomicAdd(&red[(0 * GR + lr) * NH + head], ps);
            atomicAdd(&red[(1 * GR + lr) * NH + head], pd);
        }
    }
    __syncthreads();
    for (int idx = t; idx < 2 * GR * NH; idx += GEMM_THREADS) {
        int which = idx / (GR * NH);
        int rem = idx % (GR * NH);
        int lr = rem / NH, hh = rem % NH;
        if (lr < rows) {
            float v = red[idx];
            if (which == 0) g_asrc[(r0 + lr) * NH + hh] = v;
            else            g_adst[(r0 + lr) * NH + hh] = v;
        }
    }
}

// ---------------- kgemm_hist: every block = GEMM tile, then a histogram slice ----------------
// Phase fusion: during the GEMM phase all resident blocks issue FFMA at full
// rate; finished blocks fall into the latency-bound hist phase, which overlaps
// later GEMM waves.
__global__ void __launch_bounds__(GEMM_THREADS) kgemm_hist(const float* __restrict__ x,
                                                           const float* __restrict__ W,
                                                           const float* __restrict__ att_src,
                                                           const float* __restrict__ att_dst,
                                                           int n,
                                                           const int* __restrict__ dst, int e) {
    __shared__ __align__(16) float Ws[KS * 96];
    __shared__ __align__(16) float xs[KS][XS_PAD];
    __shared__ float red[2 * GR * NH];

    gemm_block(blockIdx.x, x, W, att_src, att_dst, n, Ws, xs, red);

    // histogram slice (grid-stride over int4-packed dst ids)
    int e4 = e >> 2;
    int stride = gridDim.x * GEMM_THREADS;
    for (int i = blockIdx.x * GEMM_THREADS + threadIdx.x; i < e4; i += stride) {
        int4 d = ((const int4*)dst)[i];
        atomicAdd(&g_deg[d.x], 1);
        atomicAdd(&g_deg[d.y], 1);
        atomicAdd(&g_deg[d.z], 1);
        atomicAdd(&g_deg[d.w], 1);
    }
    if (blockIdx.x == 0 && threadIdx.x == 0) {
        for (int q = e4 * 4; q < e; q++) atomicAdd(&g_deg[dst[q]], 1);
    }
}

// ---------------- single-kernel scan with decoupled lookback ----------------
// 49 blocks, all resident in one wave; spin cannot deadlock.
__global__ void __launch_bounds__(256) kscan(int n) {
    int b = blockIdx.x, t = threadIdx.x;
    __shared__ int wsum[8], wexcl[8];
    __shared__ int offsh;
    if (t == 0) offsh = 0;

    int base = b * SCAN_TILE + t * 4;
    int v[4];
    int local = 0;
#pragma unroll
    for (int q = 0; q < 4; q++) {
        v[q] = (base + q < n) ? g_deg[base + q] : 0;
        local += v[q];
    }
    int lane = t & 31, w = t >> 5;
    int xv = local;
#pragma unroll
    for (int off = 1; off < 32; off <<= 1) {
        int y = __shfl_up_sync(0xffffffffu, xv, off);
        if (lane >= off) xv += y;
    }
    if (lane == 31) wsum[w] = xv;
    __syncthreads();
    int r = 0;
    if (t == 0) {
        for (int q = 0; q < 8; q++) { wexcl[q] = r; r += wsum[q]; }
        atomicExch(&g_bsum[b], r | 0x80000000);   // publish with flag bit 31
    }
    __syncthreads();

    // lookback: thread t polls predecessor t
    int pv = 0;
    if (t < b) {
        int pub = atomicOr(&g_bsum[t], 0);
        while (pub >= 0) {
            __nanosleep(32);
            pub = atomicOr(&g_bsum[t], 0);
        }
        pv = pub & 0x7fffffff;
    }
#pragma unroll
    for (int off = 16; off > 0; off >>= 1) pv += __shfl_down_sync(0xffffffffu, pv, off);
    if (lane == 0 && pv != 0) atomicAdd(&offsh, pv);
    __syncthreads();
    int off0 = offsh;

    int run = off0 + wexcl[w] + xv - local;
#pragma unroll
    for (int q = 0; q < 4; q++) {
        if (base + q < n) { g_rowptr[base + q] = run; g_widx[base + q] = run; }
        run += v[q];
    }
    if (b == (int)gridDim.x - 1 && t == 0) {
        int tot = 0;
        for (int q = 0; q < 8; q++) tot += wsum[q];
        g_rowptr[n] = off0 + tot;
    }
}

// ---------------- scatter: standalone, thin (high occupancy hides ATOMG latency) ----------------
__global__ void __launch_bounds__(256) kscatter(const int* __restrict__ ei, int e) {
    int e4 = e >> 2;
    int i = blockIdx.x * 256 + threadIdx.x;
    if (i < e4) {
        int4 s = ((const int4*)ei)[i];
        int4 d = ((const int4*)(ei + e))[i];
        int p0 = atomicAdd(&g_widx[d.x], 1); g_csr[p0] = s.x;
        int p1 = atomicAdd(&g_widx[d.y], 1); g_csr[p1] = s.y;
        int p2 = atomicAdd(&g_widx[d.z], 1); g_csr[p2] = s.z;
        int p3 = atomicAdd(&g_widx[d.w], 1); g_csr[p3] = s.w;
    }
    if (i == e4) {
        for (int q = e4 * 4; q < e; q++) {
            int pos = atomicAdd(&g_widx[ei[e + q]], 1);
            g_csr[pos] = ei[q];
        }
    }
}

// ---------------- kmain: warp-per-node, float4 channels ----------------
#define WCHUNK 32
__global__ void __launch_bounds__(256) kmain(const float* __restrict__ x,
                                             const float* __restrict__ bias,
                                             const float* __restrict__ gamma,
                                             const float* __restrict__ beta,
                                             float* __restrict__ out, int n) {
    int warp = threadIdx.x >> 5;
    int lane = threadIdx.x & 31;
    int i = blockIdx.x * 8 + warp;
    if (i >= n) return;

    __shared__ float ws[8][WCHUNK][NH];
    __shared__ int   ss[8][WCHUNK];

    int row0 = __ldg(&g_rowptr[i]);
    int deg  = __ldg(&g_rowptr[i + 1]) - row0;
    float4 ad = __ldg((const float4*)&g_adst[i * NH]);

    int cidx = (lane < 24) ? lane : 0;
    int head = cidx / 6;
    const float4* h4 = (const float4*)g_h;

    float4 acc = make_float4(0.f, 0.f, 0.f, 0.f);
    float ssum = 0.f;

    for (int bse = 0; bse < deg; bse += WCHUNK) {
        int cnt = min(WCHUNK, deg - bse);
        if (lane < cnt) {
            int src = __ldg(&g_csr[row0 + bse + lane]);
            ss[warp][lane] = src;
            float4 as = __ldg((const float4*)&g_asrc[src * NH]);
            float e0 = as.x + ad.x, e1 = as.y + ad.y, e2 = as.z + ad.z, e3 = as.w + ad.w;
            e0 = (e0 > 0.f) ? e0 : NEG_SLOPE * e0;
            e1 = (e1 > 0.f) ? e1 : NEG_SLOPE * e1;
            e2 = (e2 > 0.f) ? e2 : NEG_SLOPE * e2;
            e3 = (e3 > 0.f) ? e3 : NEG_SLOPE * e3;
            ws[warp][lane][0] = __expf(e0);
            ws[warp][lane][1] = __expf(e1);
            ws[warp][lane][2] = __expf(e2);
            ws[warp][lane][3] = __expf(e3);
        }
        __syncwarp();
        if (lane < 24) {
#pragma unroll 4
            for (int j = 0; j < cnt; j++) {
                float wv = ws[warp][j][head];
                float4 h = __ldg(&h4[ss[warp][j] * 24 + lane]);
                ssum += wv;
                acc.x += wv * h.x;
                acc.y += wv * h.y;
                acc.z += wv * h.z;
                acc.w += wv * h.w;
            }
        }
        __syncwarp();
    }

    // self loop + bias + residual
    float4 o = make_float4(0.f, 0.f, 0.f, 0.f);
    if (lane < 24) {
        float4 asi = __ldg((const float4*)&g_asrc[i * NH]);
        float es[4];
        es[0] = asi.x + ad.x; es[1] = asi.y + ad.y; es[2] = asi.z + ad.z; es[3] = asi.w + ad.w;
#pragma unroll
        for (int q = 0; q < 4; q++) es[q] = (es[q] > 0.f) ? es[q] : NEG_SLOPE * es[q];
        float wself = __expf(es[head]);
        float4 hi = __ldg(&h4[i * 24 + lane]);
        ssum += wself;
        acc.x += wself * hi.x; acc.y += wself * hi.y;
        acc.z += wself * hi.z; acc.w += wself * hi.w;
        float inv_s = 1.f / (ssum + 1e-16f);
        float4 bv = __ldg((const float4*)&bias[lane * 4]);
        float4 xv = __ldg(&((const float4*)x)[i * 24 + lane]);
        o.x = acc.x * inv_s + bv.x + xv.x;
        o.y = acc.y * inv_s + bv.y + xv.y;
        o.z = acc.z * inv_s + bv.z + xv.z;
        o.w = acc.w * inv_s + bv.w + xv.w;
    }

    // LayerNorm over 96 channels (warp reduce, lanes>=24 contribute 0)
    float v1 = (lane < 24) ? (o.x + o.y) + (o.z + o.w) : 0.f;
    float v2 = (lane < 24) ? (o.x * o.x + o.y * o.y) + (o.z * o.z + o.w * o.w) : 0.f;
#pragma unroll
    for (int off = 16; off > 0; off >>= 1) {
        v1 += __shfl_down_sync(0xffffffffu, v1, off);
        v2 += __shfl_down_sync(0xffffffffu, v2, off);
    }
    float mu  = __shfl_sync(0xffffffffu, v1, 0) * (1.f / 96.f);
    float msq = __shfl_sync(0xffffffffu, v2, 0) * (1.f / 96.f);
    float inv = rsqrtf(msq - mu * mu + LN_EPS);

    if (lane < 24) {
        float4 gv = __ldg((const float4*)&gamma[lane * 4]);
        float4 btv = __ldg((const float4*)&beta[lane * 4]);
        float4 y;
        y.x = fmaxf((o.x - mu) * inv * gv.x + btv.x, 0.f);
        y.y = fmaxf((o.y - mu) * inv * gv.y + btv.y, 0.f);
        y.z = fmaxf((o.z - mu) * inv * gv.z + btv.z, 0.f);
        y.w = fmaxf((o.w - mu) * inv * gv.w + btv.w, 0.f);
        ((float4*)out)[i * 24 + lane] = y;
    }
}

// ---------------- launch ----------------
extern "C" void kernel_launch(void* const* d_in, const int* in_sizes, int n_in,
                              void* d_out, int out_size) {
    const float* x        = (const float*)d_in[0];
    const int*   ei       = (const int*)d_in[1];
    const float* W        = (const float*)d_in[2];
    const float* att_src  = (const float*)d_in[3];
    const float* att_dst  = (const float*)d_in[4];
    const float* bias     = (const float*)d_in[5];
    const float* gamma    = (const float*)d_in[6];
    const float* beta     = (const float*)d_in[7];
    float* out = (float*)d_out;

    int n = in_sizes[0] / C;       // 50000
    int e = in_sizes[1] / 2;       // 800000
    int e4 = e >> 2;

    int gemm_blocks = (n + GR - 1) / GR;          // 782

    kzero<<<(n + 255) / 256, 256>>>(n);
    kgemm_hist<<<gemm_blocks, GEMM_THREADS>>>(x, W, att_src, att_dst, n, ei + e, e);
    kscan<<<NBLK_SCAN, 256>>>(n);
    kscatter<<<(e4 + 256) / 256, 256>>>(ei, e);
    kmain<<<(n + 7) / 8, 256>>>(x, bias, gamma, beta, out, n);
}

// round 11
// speedup vs baseline: 1.0769x; 1.0769x over previous
#include <cuda_runtime.h>
#include <math.h>

// Problem constants (fixed by reference: N=50000, E=800000, C=96, H=4, CH=24)
#define NMAX 50000
#define EMAX 800000
#define C 96
#define NH 4
#define CH 24
#define NEG_SLOPE 0.2f
#define LN_EPS 1e-5f

// ---------------- device scratch (static, no allocation) ----------------
__device__ float g_h[NMAX * C];        // 19.2 MB
__device__ float g_asrc[NMAX * NH];
__device__ float g_adst[NMAX * NH];
__device__ int   g_deg[NMAX];
__device__ int   g_rowptr[NMAX + 1];
__device__ int   g_widx[NMAX];
__device__ int   g_csr[EMAX];

#define SCAN_TILE 1024
#define NBLK_SCAN ((NMAX + SCAN_TILE - 1) / SCAN_TILE)   // 49
__device__ int g_bsum[NBLK_SCAN];

// ---------------- packed f32x2 helpers (Blackwell FFMA2, PTX-only) ----------------
__device__ __forceinline__ unsigned long long pack2(float a, float b) {
    unsigned long long r;
    asm("mov.b64 %0, {%1, %2};" : "=l"(r) : "f"(a), "f"(b));
    return r;
}
__device__ __forceinline__ unsigned long long fma2(unsigned long long a,
                                                   unsigned long long b,
                                                   unsigned long long c) {
    unsigned long long d;
    asm("fma.rn.f32x2 %0, %1, %2, %3;" : "=l"(d) : "l"(a), "l"(b), "l"(c));
    return d;
}
__device__ __forceinline__ void unpack2(unsigned long long v, float& lo, float& hi) {
    asm("mov.b64 {%0, %1}, %2;" : "=f"(lo), "=f"(hi) : "l"(v));
}

// ---------------- zero counters (deg + scan flags) ----------------
__global__ void kzero(int n) {
    int i = blockIdx.x * blockDim.x + threadIdx.x;
    if (i < n) g_deg[i] = 0;
    if (i < NBLK_SCAN) g_bsum[i] = 0;
}

// ================= GEMM tile (h = x@W + fused attention coeffs), FFMA2 =================
#define GR 64
#define GEMM_THREADS 192
#define KS 24
#define XS_PAD 68

__device__ __forceinline__ void gemm_block(int gb,
                                           const float* __restrict__ x,
                                           const float* __restrict__ W,
                                           const float* __restrict__ att_src,
                                           const float* __restrict__ att_dst,
                                           int n,
                                           float* Ws, float (*xs)[XS_PAD], float* red) {
    int t = threadIdx.x;
    int r0 = gb * GR;
    int rows = min(GR, n - r0);

    for (int idx = t; idx < 2 * GR * NH; idx += GEMM_THREADS) red[idx] = 0.f;

    int tc = t % 24;   // cols tc*4..+3
    int tr = t / 24;   // rows tr*8..+7 (4 row-pairs)
    // acc2[p][q]: rows (tr*8+2p, tr*8+2p+1), col tc*4+q, packed f32x2
    unsigned long long acc2[4][4];
#pragma unroll
    for (int p = 0; p < 4; p++)
#pragma unroll
        for (int q = 0; q < 4; q++) acc2[p][q] = 0ull;

    for (int ks = 0; ks < 96; ks += KS) {
        for (int idx = t; idx < KS * 96; idx += GEMM_THREADS)
            Ws[idx] = W[(ks + idx / 96) * 96 + idx % 96];
        for (int idx = t; idx < rows * KS; idx += GEMM_THREADS) {
            int r = idx / KS, k = idx % KS;
            xs[k][r] = x[(r0 + r) * 96 + ks + k];
        }
        __syncthreads();
#pragma unroll 4
        for (int k = 0; k < KS; k++) {
            float4 wv = *(const float4*)&Ws[k * 96 + tc * 4];
            unsigned long long w2[4];
            w2[0] = pack2(wv.x, wv.x);
            w2[1] = pack2(wv.y, wv.y);
            w2[2] = pack2(wv.z, wv.z);
            w2[3] = pack2(wv.w, wv.w);
            // two 16B loads give 4 row-pairs, already packed
            ulonglong2 xA = *(const ulonglong2*)&xs[k][tr * 8];
            ulonglong2 xB = *(const ulonglong2*)&xs[k][tr * 8 + 4];
            unsigned long long xp[4] = {xA.x, xA.y, xB.x, xB.y};
#pragma unroll
            for (int p = 0; p < 4; p++) {
                acc2[p][0] = fma2(xp[p], w2[0], acc2[p][0]);
                acc2[p][1] = fma2(xp[p], w2[1], acc2[p][1]);
                acc2[p][2] = fma2(xp[p], w2[2], acc2[p][2]);
                acc2[p][3] = fma2(xp[p], w2[3], acc2[p][3]);
            }
        }
        __syncthreads();
    }

    // unpack to per-row values
    float acc[8][4];
#pragma unroll
    for (int p = 0; p < 4; p++)
#pragma unroll
        for (int q = 0; q < 4; q++)
            unpack2(acc2[p][q], acc[2 * p][q], acc[2 * p + 1][q]);

#pragma unroll
    for (int p = 0; p < 8; p++) {
        int gr = r0 + tr * 8 + p;
        if (gr < n) {
            float4 st = make_float4(acc[p][0], acc[p][1], acc[p][2], acc[p][3]);
            *(float4*)&g_h[gr * 96 + tc * 4] = st;
        }
    }

    int col0 = tc * 4;
    int head = tc / 6;
    float4 asv = *(const float4*)&att_src[col0];
    float4 adv = *(const float4*)&att_dst[col0];
#pragma unroll
    for (int p = 0; p < 8; p++) {
        int lr = tr * 8 + p;
        if (lr < rows) {
            float ps = acc[p][0] * asv.x + acc[p][1] * asv.y + acc[p][2] * asv.z + acc[p][3] * asv.w;
            float pd = acc[p][0] * adv.x + acc[p][1] * adv.y + acc[p][2] * adv.z + acc[p][3] * adv.w;
            atomicAdd(&red[(0 * GR + lr) * NH + head], ps);
            atomicAdd(&red[(1 * GR + lr) * NH + head], pd);
        }
    }
    __syncthreads();
    for (int idx = t; idx < 2 * GR * NH; idx += GEMM_THREADS) {
        int which = idx / (GR * NH);
        int rem = idx % (GR * NH);
        int lr = rem / NH, hh = rem % NH;
        if (lr < rows) {
            float v = red[idx];
            if (which == 0) g_asrc[(r0 + lr) * NH + hh] = v;
            else            g_adst[(r0 + lr) * NH + hh] = v;
        }
    }
}

// fused1: gemm rows [0, GB1*GR) + histogram of dst (block-range fusion, proven in R8)
__global__ void __launch_bounds__(GEMM_THREADS) kfused1(const float* __restrict__ x,
                                                        const float* __restrict__ W,
                                                        const float* __restrict__ att_src,
                                                        const float* __restrict__ att_dst,
                                                        int n, int GB1,
                                                        const int* __restrict__ dst, int e) {
    __shared__ __align__(16) float Ws[KS * 96];
    __shared__ __align__(16) float xs[KS][XS_PAD];
    __shared__ float red[2 * GR * NH];
    if ((int)blockIdx.x < GB1) {
        gemm_block(blockIdx.x, x, W, att_src, att_dst, n, Ws, xs, red);
    } else {
        int e4 = e >> 2;
        int i = (blockIdx.x - GB1) * GEMM_THREADS + threadIdx.x;
        if (i < e4) {
            int4 d = ((const int4*)dst)[i];
            atomicAdd(&g_deg[d.x], 1);
            atomicAdd(&g_deg[d.y], 1);
            atomicAdd(&g_deg[d.z], 1);
            atomicAdd(&g_deg[d.w], 1);
        }
        if (i == e4) {
            for (int q = e4 * 4; q < e; q++) atomicAdd(&g_deg[dst[q]], 1);
        }
    }
}

// fused2: gemm rows [GB1*GR, n) + scatter src ids into CSR
__global__ void __launch_bounds__(GEMM_THREADS) kfused2(const float* __restrict__ x,
                                                        const float* __restrict__ W,
                                                        const float* __restrict__ att_src,
                                                        const float* __restrict__ att_dst,
                                                        int n, int GB1, int GB2,
                                                        const int* __restrict__ ei, int e) {
    __shared__ __align__(16) float Ws[KS * 96];
    __shared__ __align__(16) float xs[KS][XS_PAD];
    __shared__ float red[2 * GR * NH];
    if ((int)blockIdx.x < GB2) {
        gemm_block(GB1 + blockIdx.x, x, W, att_src, att_dst, n, Ws, xs, red);
    } else {
        int e4 = e >> 2;
        int i = (blockIdx.x - GB2) * GEMM_THREADS + threadIdx.x;
        if (i < e4) {
            int4 s = ((const int4*)ei)[i];
            int4 d = ((const int4*)(ei + e))[i];
            int p0 = atomicAdd(&g_widx[d.x], 1); g_csr[p0] = s.x;
            int p1 = atomicAdd(&g_widx[d.y], 1); g_csr[p1] = s.y;
            int p2 = atomicAdd(&g_widx[d.z], 1); g_csr[p2] = s.z;
            int p3 = atomicAdd(&g_widx[d.w], 1); g_csr[p3] = s.w;
        }
        if (i == e4) {
            for (int q = e4 * 4; q < e; q++) {
                int pos = atomicAdd(&g_widx[ei[e + q]], 1);
                g_csr[pos] = ei[q];
            }
        }
    }
}

// ---------------- single-kernel scan with decoupled lookback ----------------
__global__ void __launch_bounds__(256) kscan(int n) {
    int b = blockIdx.x, t = threadIdx.x;
    __shared__ int wsum[8], wexcl[8];
    __shared__ int offsh;
    if (t == 0) offsh = 0;

    int base = b * SCAN_TILE + t * 4;
    int v[4];
    int local = 0;
#pragma unroll
    for (int q = 0; q < 4; q++) {
        v[q] = (base + q < n) ? g_deg[base + q] : 0;
        local += v[q];
    }
    int lane = t & 31, w = t >> 5;
    int xv = local;
#pragma unroll
    for (int off = 1; off < 32; off <<= 1) {
        int y = __shfl_up_sync(0xffffffffu, xv, off);
        if (lane >= off) xv += y;
    }
    if (lane == 31) wsum[w] = xv;
    __syncthreads();
    int r = 0;
    if (t == 0) {
        for (int q = 0; q < 8; q++) { wexcl[q] = r; r += wsum[q]; }
        atomicExch(&g_bsum[b], r | 0x80000000);   // publish with flag bit 31
    }
    __syncthreads();

    int pv = 0;
    if (t < b) {
        int pub = atomicOr(&g_bsum[t], 0);
        while (pub >= 0) {
            __nanosleep(32);
            pub = atomicOr(&g_bsum[t], 0);
        }
        pv = pub & 0x7fffffff;
    }
#pragma unroll
    for (int off = 16; off > 0; off >>= 1) pv += __shfl_down_sync(0xffffffffu, pv, off);
    if (lane == 0 && pv != 0) atomicAdd(&offsh, pv);
    __syncthreads();
    int off0 = offsh;

    int run = off0 + wexcl[w] + xv - local;
#pragma unroll
    for (int q = 0; q < 4; q++) {
        if (base + q < n) { g_rowptr[base + q] = run; g_widx[base + q] = run; }
        run += v[q];
    }
    if (b == (int)gridDim.x - 1 && t == 0) {
        int tot = 0;
        for (int q = 0; q < 8; q++) tot += wsum[q];
        g_rowptr[n] = off0 + tot;
    }
}

// ---------------- kmain: warp-per-node, float4 channels ----------------
#define WCHUNK 32
__global__ void __launch_bounds__(256) kmain(const float* __restrict__ x,
                                             const float* __restrict__ bias,
                                             const float* __restrict__ gamma,
                                             const float* __restrict__ beta,
                                             float* __restrict__ out, int n) {
    int warp = threadIdx.x >> 5;
    int lane = threadIdx.x & 31;
    int i = blockIdx.x * 8 + warp;
    if (i >= n) return;

    __shared__ float ws[8][WCHUNK][NH];
    __shared__ int   ss[8][WCHUNK];

    int row0 = __ldg(&g_rowptr[i]);
    int deg  = __ldg(&g_rowptr[i + 1]) - row0;
    float4 ad = __ldg((const float4*)&g_adst[i * NH]);

    int cidx = (lane < 24) ? lane : 0;
    int head = cidx / 6;
    const float4* h4 = (const float4*)g_h;

    float4 acc = make_float4(0.f, 0.f, 0.f, 0.f);
    float ssum = 0.f;

    for (int bse = 0; bse < deg; bse += WCHUNK) {
        int cnt = min(WCHUNK, deg - bse);
        if (lane < cnt) {
            int src = __ldg(&g_csr[row0 + bse + lane]);
            ss[warp][lane] = src;
            float4 as = __ldg((const float4*)&g_asrc[src * NH]);
            float e0 = as.x + ad.x, e1 = as.y + ad.y, e2 = as.z + ad.z, e3 = as.w + ad.w;
            e0 = (e0 > 0.f) ? e0 : NEG_SLOPE * e0;
            e1 = (e1 > 0.f) ? e1 : NEG_SLOPE * e1;
            e2 = (e2 > 0.f) ? e2 : NEG_SLOPE * e2;
            e3 = (e3 > 0.f) ? e3 : NEG_SLOPE * e3;
            ws[warp][lane][0] = __expf(e0);
            ws[warp][lane][1] = __expf(e1);
            ws[warp][lane][2] = __expf(e2);
            ws[warp][lane][3] = __expf(e3);
        }
        __syncwarp();
        if (lane < 24) {
#pragma unroll 4
            for (int j = 0; j < cnt; j++) {
                float wv = ws[warp][j][head];
                float4 h = __ldg(&h4[ss[warp][j] * 24 + lane]);
                ssum += wv;
                acc.x += wv * h.x;
                acc.y += wv * h.y;
                acc.z += wv * h.z;
                acc.w += wv * h.w;
            }
        }
        __syncwarp();
    }

    float4 o = make_float4(0.f, 0.f, 0.f, 0.f);
    if (lane < 24) {
        float4 asi = __ldg((const float4*)&g_asrc[i * NH]);
        float es[4];
        es[0] = asi.x + ad.x; es[1] = asi.y + ad.y; es[2] = asi.z + ad.z; es[3] = asi.w + ad.w;
#pragma unroll
        for (int q = 0; q < 4; q++) es[q] = (es[q] > 0.f) ? es[q] : NEG_SLOPE * es[q];
        float wself = __expf(es[head]);
        float4 hi = __ldg(&h4[i * 24 + lane]);
        ssum += wself;
        acc.x += wself * hi.x; acc.y += wself * hi.y;
        acc.z += wself * hi.z; acc.w += wself * hi.w;
        float inv_s = 1.f / (ssum + 1e-16f);
        float4 bv = __ldg((const float4*)&bias[lane * 4]);
        float4 xv = __ldg(&((const float4*)x)[i * 24 + lane]);
        o.x = acc.x * inv_s + bv.x + xv.x;
        o.y = acc.y * inv_s + bv.y + xv.y;
        o.z = acc.z * inv_s + bv.z + xv.z;
        o.w = acc.w * inv_s + bv.w + xv.w;
    }

    float v1 = (lane < 24) ? (o.x + o.y) + (o.z + o.w) : 0.f;
    float v2 = (lane < 24) ? (o.x * o.x + o.y * o.y) + (o.z * o.z + o.w * o.w) : 0.f;
#pragma unroll
    for (int off = 16; off > 0; off >>= 1) {
        v1 += __shfl_down_sync(0xffffffffu, v1, off);
        v2 += __shfl_down_sync(0xffffffffu, v2, off);
    }
    float mu  = __shfl_sync(0xffffffffu, v1, 0) * (1.f / 96.f);
    float msq = __shfl_sync(0xffffffffu, v2, 0) * (1.f / 96.f);
    float inv = rsqrtf(msq - mu * mu + LN_EPS);

    if (lane < 24) {
        float4 gv = __ldg((const float4*)&gamma[lane * 4]);
        float4 btv = __ldg((const float4*)&beta[lane * 4]);
        float4 y;
        y.x = fmaxf((o.x - mu) * inv * gv.x + btv.x, 0.f);
        y.y = fmaxf((o.y - mu) * inv * gv.y + btv.y, 0.f);
        y.z = fmaxf((o.z - mu) * inv * gv.z + btv.z, 0.f);
        y.w = fmaxf((o.w - mu) * inv * gv.w + btv.w, 0.f);
        ((float4*)out)[i * 24 + lane] = y;
    }
}

// ---------------- launch ----------------
extern "C" void kernel_launch(void* const* d_in, const int* in_sizes, int n_in,
                              void* d_out, int out_size) {
    const float* x        = (const float*)d_in[0];
    const int*   ei       = (const int*)d_in[1];
    const float* W        = (const float*)d_in[2];
    const float* att_src  = (const float*)d_in[3];
    const float* att_dst  = (const float*)d_in[4];
    const float* bias     = (const float*)d_in[5];
    const float* gamma    = (const float*)d_in[6];
    const float* beta     = (const float*)d_in[7];
    float* out = (float*)d_out;

    int n = in_sizes[0] / C;       // 50000
    int e = in_sizes[1] / 2;       // 800000
    int e4 = e >> 2;

    int gemm_blocks = (n + GR - 1) / GR;          // 782
    int GB1 = (gemm_blocks + 1) / 2;
    int GB2 = gemm_blocks - GB1;
    int csr_blocks = (e4 + GEMM_THREADS) / GEMM_THREADS;

    kzero<<<(n + 255) / 256, 256>>>(n);
    kfused1<<<GB1 + csr_blocks, GEMM_THREADS>>>(x, W, att_src, att_dst, n, GB1, ei + e, e);
    kscan<<<NBLK_SCAN, 256>>>(n);
    kfused2<<<GB2 + csr_blocks, GEMM_THREADS>>>(x, W, att_src, att_dst, n, GB1, GB2, ei, e);
    kmain<<<(n + 7) / 8, 256>>>(x, bias, gamma, beta, out, n);
}